// round 1
// baseline (speedup 1.0000x reference)
#include <cuda_runtime.h>
#include <math.h>

// ---------------------------------------------------------------------------
// Problem constants: x[B=32, L=256, N=1024] fp32, weight[256,256], bias[256]
// B*L = 8192 ("K" of the Gram / row dim of output GEMM)
// ---------------------------------------------------------------------------
#define Bv 32
#define Lv 256
#define Nv 1024
#define BLv 8192
#define KTOP 307
#define SPLITK 8

// Scratch (device globals: allocation-free rule)
__device__ float g_xhat[BLv * Nv];          // [k, n]  (k-major rows of 1024)
__device__ float g_simpart[SPLITK * Nv * Nv];
__device__ float g_sim[Nv * Nv];
__device__ float g_A[Nv * Nv];
__device__ float g_An[Nv * Nv];
__device__ float g_dinv[Nv];
__device__ float g_invn[Bv * Nv];           // [b, n]
__device__ float g_Yt[BLv * Nv];            // [s, k] : xw transposed, s-major rows of 8192

// ---------------------------------------------------------------------------
// 1) per-(n,b) inverse L2 norm over L.  Coalesced over n.
// ---------------------------------------------------------------------------
__global__ void colsumsq_kernel(const float* __restrict__ x, float* __restrict__ invn) {
    int n = blockIdx.x * 256 + threadIdx.x;   // grid (4, 32)
    int b = blockIdx.y;
    const float* p = x + (long long)b * Lv * Nv + n;
    float s = 0.f;
#pragma unroll 8
    for (int l = 0; l < Lv; l++) {
        float v = p[(long long)l * Nv];
        s += v * v;
    }
    invn[b * Nv + n] = 1.0f / fmaxf(sqrtf(s), 1e-12f);
}

// ---------------------------------------------------------------------------
// 2) x̂[k, n] = x[k, n] * invn[b(k), n]   (elementwise, float4)
// ---------------------------------------------------------------------------
__global__ void scale_x_kernel(const float* __restrict__ x, const float* __restrict__ invn,
                               float* __restrict__ xhat) {
    long long i4 = (long long)blockIdx.x * blockDim.x + threadIdx.x;  // over 2M float4
    long long k = i4 >> 8;          // 256 float4 per row of 1024 floats
    int b = (int)(k >> 8);
    int c4 = (int)(i4 & 255);
    float4 xv = ((const float4*)x)[i4];
    float4 sv = ((const float4*)(invn + b * Nv))[c4];
    float4 r;
    r.x = xv.x * sv.x; r.y = xv.y * sv.y; r.z = xv.z * sv.z; r.w = xv.w * sv.w;
    ((float4*)xhat)[i4] = r;
}

// ---------------------------------------------------------------------------
// Generic TN SGEMM:  C[m,n] = alpha * sum_k A[k,m] * B[k,n]  (+ bias[m&255])
// Both operands K-major. 128x128 block, BK=8, 256 threads, 8x8 per thread.
// All dims must be multiples of 128/8 (they are). Simple reg-prefetch pipeline.
// ---------------------------------------------------------------------------
#define BM 128
#define BN 128
#define BK 8

__global__ void __launch_bounds__(256)
sgemm_tn(const float* __restrict__ Ag, const float* __restrict__ Bg, float* __restrict__ Cg,
         int K, int lda, int ldb, int ldc,
         long long sA, long long sB, long long sC,
         float alpha, const float* __restrict__ bias) {
    const float* A = Ag + (long long)blockIdx.z * sA;
    const float* B = Bg + (long long)blockIdx.z * sB;
    float* C = Cg + (long long)blockIdx.z * sC;

    __shared__ float As[BK][BM];
    __shared__ float Bs[BK][BN];

    int tid = threadIdx.x;
    int m0 = blockIdx.y * BM;
    int n0 = blockIdx.x * BN;

    int lk = tid >> 5;          // 0..7
    int lm = (tid & 31) << 2;   // 0..124 step 4
    const float* Aload = A + (long long)lk * lda + m0 + lm;
    const float* Bload = B + (long long)lk * ldb + n0 + lm;

    int tx = tid & 15, ty = tid >> 4;

    float c[8][8];
#pragma unroll
    for (int i = 0; i < 8; i++)
#pragma unroll
        for (int j = 0; j < 8; j++) c[i][j] = 0.f;

    float4 av = *(const float4*)(Aload);
    float4 bv = *(const float4*)(Bload);

    for (int k0 = 0; k0 < K; k0 += BK) {
        *(float4*)(&As[lk][lm]) = av;
        *(float4*)(&Bs[lk][lm]) = bv;
        __syncthreads();

        if (k0 + BK < K) {
            Aload += (long long)BK * lda;
            Bload += (long long)BK * ldb;
            av = *(const float4*)(Aload);
            bv = *(const float4*)(Bload);
        }

#pragma unroll
        for (int kk = 0; kk < BK; kk++) {
            float a[8], b[8];
            *(float4*)(a)     = *(const float4*)(&As[kk][ty * 4]);
            *(float4*)(a + 4) = *(const float4*)(&As[kk][64 + ty * 4]);
            *(float4*)(b)     = *(const float4*)(&Bs[kk][tx * 4]);
            *(float4*)(b + 4) = *(const float4*)(&Bs[kk][64 + tx * 4]);
#pragma unroll
            for (int i = 0; i < 8; i++)
#pragma unroll
                for (int j = 0; j < 8; j++)
                    c[i][j] += a[i] * b[j];
        }
        __syncthreads();
    }

#pragma unroll
    for (int i = 0; i < 8; i++) {
        int m = m0 + ((i < 4) ? (ty * 4 + i) : (64 + ty * 4 + (i - 4)));
        float bb = bias ? bias[m & 255] : 0.f;
#pragma unroll
        for (int jh = 0; jh < 2; jh++) {
            int n = n0 + jh * 64 + tx * 4;
            float4 v;
            v.x = alpha * c[i][jh * 4 + 0] + bb;
            v.y = alpha * c[i][jh * 4 + 1] + bb;
            v.z = alpha * c[i][jh * 4 + 2] + bb;
            v.w = alpha * c[i][jh * 4 + 3] + bb;
            *(float4*)(&C[(long long)m * ldc + n]) = v;
        }
    }
}

// ---------------------------------------------------------------------------
// 3b) Deterministic ordered reduce of split-K partials, * 1/B
// ---------------------------------------------------------------------------
__global__ void reduce_sim_kernel(const float* __restrict__ part, float* __restrict__ sim) {
    long long i4 = (long long)blockIdx.x * blockDim.x + threadIdx.x;  // 256K float4
    float4 acc = make_float4(0.f, 0.f, 0.f, 0.f);
#pragma unroll
    for (int z = 0; z < SPLITK; z++) {
        float4 v = ((const float4*)(part + (long long)z * Nv * Nv))[i4];
        acc.x += v.x; acc.y += v.y; acc.z += v.z; acc.w += v.w;
    }
    const float inv = 1.0f / (float)Bv;
    acc.x *= inv; acc.y *= inv; acc.z *= inv; acc.w *= inv;
    ((float4*)sim)[i4] = acc;
}

// ---------------------------------------------------------------------------
// 4) Exact per-row top-k via in-shared bitonic sort of packed (value, 1023-idx)
//    keys. Descending sort; ties -> lower index first (matches lax.top_k).
//    Keep first KTOP non-self entries; A[n,m] = sim if kept else 0.
// ---------------------------------------------------------------------------
__global__ void topk_rows_kernel(const float* __restrict__ sim, float* __restrict__ A) {
    __shared__ unsigned long long s[Nv];
    __shared__ int selfpos;
    int n = blockIdx.x;
    int t = threadIdx.x;  // 512 threads

    for (int i = t; i < Nv; i += 512) {
        unsigned u = __float_as_uint(sim[n * Nv + i]);
        u = (u & 0x80000000u) ? ~u : (u | 0x80000000u);  // order-preserving map
        s[i] = ((unsigned long long)u << 32) | (unsigned)(1023 - i);
    }
    if (t == 0) selfpos = 0;
    __syncthreads();

    for (unsigned k = 2; k <= (unsigned)Nv; k <<= 1) {
        for (unsigned j = k >> 1; j > 0; j >>= 1) {
            for (int i = t; i < Nv; i += 512) {
                int ixj = i ^ (int)j;
                if (ixj > i) {
                    bool dirDesc = ((i & k) == 0);
                    unsigned long long a = s[i], b = s[ixj];
                    bool sw = dirDesc ? (a < b) : (a > b);
                    if (sw) { s[i] = b; s[ixj] = a; }
                }
            }
            __syncthreads();
        }
    }

    for (int i = t; i < Nv; i += 512) {
        unsigned idx = 1023u - (unsigned)(s[i] & 0xFFFFFFFFu);
        if (idx == (unsigned)n) selfpos = i;
    }
    __syncthreads();
    int sp = selfpos;

    for (int p = t; p < Nv; p += 512) {
        unsigned long long e = s[p];
        unsigned idx = 1023u - (unsigned)(e & 0xFFFFFFFFu);
        unsigned u = (unsigned)(e >> 32);
        u = (u & 0x80000000u) ? (u & 0x7FFFFFFFu) : ~u;  // inverse map
        float v = __uint_as_float(u);
        int rank = p - (p > sp ? 1 : 0);
        bool keep = (p != sp) && (rank < KTOP);
        A[n * Nv + idx] = keep ? v : 0.f;
    }
}

// ---------------------------------------------------------------------------
// 5) in-degree (column sum) -> dinv
// ---------------------------------------------------------------------------
__global__ void deg_kernel(const float* __restrict__ A, float* __restrict__ dinv) {
    int d = blockIdx.x * 256 + threadIdx.x;  // grid 4
    float sum = 0.f;
    for (int src = 0; src < Nv; src++) sum += A[src * Nv + d];
    dinv[d] = (sum > 0.f) ? rsqrtf(sum) : 0.f;
}

// ---------------------------------------------------------------------------
// 6) An[s,d] = dinv[s] * A[s,d] * dinv[d]
// ---------------------------------------------------------------------------
__global__ void an_kernel(const float* __restrict__ A, const float* __restrict__ dinv,
                          float* __restrict__ An) {
    int i = blockIdx.x * 256 + threadIdx.x;  // grid 4096 over 1M
    int src = i >> 10, d = i & 1023;
    An[i] = dinv[src] * A[i] * dinv[d];
}

// ---------------------------------------------------------------------------
// Launch
// ---------------------------------------------------------------------------
extern "C" void kernel_launch(void* const* d_in, const int* in_sizes, int n_in,
                              void* d_out, int out_size) {
    const float* x    = (const float*)d_in[0];   // [32,256,1024]
    const float* W    = (const float*)d_in[1];   // [256,256]
    const float* bias = (const float*)d_in[2];   // [256]
    float* out = (float*)d_out;                  // [32,256,1024] = [k, d]

    float *xhat, *simpart, *sim, *A, *An, *dinv, *invn, *Yt;
    cudaGetSymbolAddress((void**)&xhat,    g_xhat);
    cudaGetSymbolAddress((void**)&simpart, g_simpart);
    cudaGetSymbolAddress((void**)&sim,     g_sim);
    cudaGetSymbolAddress((void**)&A,       g_A);
    cudaGetSymbolAddress((void**)&An,      g_An);
    cudaGetSymbolAddress((void**)&dinv,    g_dinv);
    cudaGetSymbolAddress((void**)&invn,    g_invn);
    cudaGetSymbolAddress((void**)&Yt,      g_Yt);

    // 1) norms
    colsumsq_kernel<<<dim3(Nv / 256, Bv), 256>>>(x, invn);

    // 2) x̂
    scale_x_kernel<<<(BLv * Nv / 4) / 256, 256>>>(x, invn, xhat);

    // 3) Gram split-K: simpart[z] = x̂_zᵀ x̂_z  (K chunk = 1024 each)
    sgemm_tn<<<dim3(Nv / BN, Nv / BM, SPLITK), 256>>>(
        xhat, xhat, simpart,
        /*K=*/BLv / SPLITK, /*lda=*/Nv, /*ldb=*/Nv, /*ldc=*/Nv,
        /*sA=*/(long long)(BLv / SPLITK) * Nv, /*sB=*/(long long)(BLv / SPLITK) * Nv,
        /*sC=*/(long long)Nv * Nv, 1.0f, nullptr);

    // 3b) ordered reduce + /B
    reduce_sim_kernel<<<(Nv * Nv / 4) / 256, 256>>>(simpart, sim);

    // 4) exact top-k -> A
    topk_rows_kernel<<<Nv, 512>>>(sim, A);

    // 5) degree -> dinv
    deg_kernel<<<Nv / 256, 256>>>(A, dinv);

    // 6) An
    an_kernel<<<(Nv * Nv) / 256, 256>>>(A, dinv, An);

    // 7) Yt[s, (b,o)] = sum_l x[(b,l),s] * W[l,o]   (batched over b)
    sgemm_tn<<<dim3(Lv / BN, Nv / BM, Bv), 256>>>(
        x, W, Yt,
        /*K=*/Lv, /*lda=*/Nv, /*ldb=*/Lv, /*ldc=*/BLv,
        /*sA=*/(long long)Lv * Nv, /*sB=*/0, /*sC=*/Lv, 1.0f, nullptr);

    // 8) out[k, d] = sum_s Yt[s,k] * An[s,d] + bias[k%256]
    sgemm_tn<<<dim3(Nv / BN, BLv / BM, 1), 256>>>(
        Yt, An, out,
        /*K=*/Nv, /*lda=*/BLv, /*ldb=*/Nv, /*ldc=*/Nv,
        0, 0, 0, 1.0f, bias);
}

// round 2
// speedup vs baseline: 1.1528x; 1.1528x over previous
#include <cuda_runtime.h>
#include <math.h>

// ---------------------------------------------------------------------------
// Problem constants: x[B=32, L=256, N=1024] fp32, weight[256,256], bias[256]
// ---------------------------------------------------------------------------
#define Bv 32
#define Lv 256
#define Nv 1024
#define BLv 8192
#define KTOP 307
#define SPLITK 8
#define NTILE (Nv / 128)            // 8
#define NTRI (NTILE * (NTILE + 1) / 2)  // 36

// Scratch (device globals: allocation-free rule)
__device__ float g_xhat[BLv * Nv];          // [k, n]
__device__ float g_simpart[SPLITK * Nv * Nv];
__device__ float g_sim[Nv * Nv];
__device__ float g_A[Nv * Nv];
__device__ float g_An[Nv * Nv];
__device__ float g_dinv[Nv];
__device__ float g_invn[Bv * Nv];           // [b, n]
__device__ float g_Yt[BLv * Nv];            // [s, k]

// ---------------------------------------------------------------------------
// 1) per-(n,b) inverse L2 norm over L.
// ---------------------------------------------------------------------------
__global__ void colsumsq_kernel(const float* __restrict__ x, float* __restrict__ invn) {
    int n = blockIdx.x * 256 + threadIdx.x;   // grid (4, 32)
    int b = blockIdx.y;
    const float* p = x + (long long)b * Lv * Nv + n;
    float s = 0.f;
#pragma unroll 8
    for (int l = 0; l < Lv; l++) {
        float v = p[(long long)l * Nv];
        s += v * v;
    }
    invn[b * Nv + n] = 1.0f / fmaxf(sqrtf(s), 1e-12f);
}

// ---------------------------------------------------------------------------
// 2) x̂[k, n] = x[k, n] * invn[b(k), n]
// ---------------------------------------------------------------------------
__global__ void scale_x_kernel(const float* __restrict__ x, const float* __restrict__ invn,
                               float* __restrict__ xhat) {
    long long i4 = (long long)blockIdx.x * blockDim.x + threadIdx.x;
    long long k = i4 >> 8;
    int b = (int)(k >> 8);
    int c4 = (int)(i4 & 255);
    float4 xv = ((const float4*)x)[i4];
    float4 sv = ((const float4*)(invn + b * Nv))[c4];
    float4 r;
    r.x = xv.x * sv.x; r.y = xv.y * sv.y; r.z = xv.z * sv.z; r.w = xv.w * sv.w;
    ((float4*)xhat)[i4] = r;
}

// ---------------------------------------------------------------------------
// Generic TN SGEMM:  C[m,n] = alpha * sum_k A[k,m] * B[k,n]  (+ bias[m&255])
// Both operands K-major. 128x128 block, BK=8, 256 threads, 8x8 per thread.
// Double-buffered shared memory: one __syncthreads per K-iteration.
// tri=1: blockIdx.x enumerates lower-triangle tile pairs (by >= bx).
// ---------------------------------------------------------------------------
#define BM 128
#define BN 128
#define BK 8

__global__ void __launch_bounds__(256)
sgemm_tn(const float* __restrict__ Ag, const float* __restrict__ Bg, float* __restrict__ Cg,
         int K, int lda, int ldb, int ldc,
         long long sA, long long sB, long long sC,
         float alpha, const float* __restrict__ bias, int tri) {
    const float* A = Ag + (long long)blockIdx.z * sA;
    const float* B = Bg + (long long)blockIdx.z * sB;
    float* C = Cg + (long long)blockIdx.z * sC;

    int bx, by;
    if (tri) {
        int t = blockIdx.x;
        int bi = (int)((sqrtf(8.0f * (float)t + 1.0f) - 1.0f) * 0.5f);
        while ((bi + 1) * (bi + 2) / 2 <= t) bi++;
        while (bi * (bi + 1) / 2 > t) bi--;
        int bj = t - bi * (bi + 1) / 2;
        by = bi; bx = bj;            // by >= bx : lower triangle
    } else {
        bx = blockIdx.x; by = blockIdx.y;
    }

    __shared__ float As[2][BK][BM];
    __shared__ float Bs[2][BK][BN];

    int tid = threadIdx.x;
    int m0 = by * BM;
    int n0 = bx * BN;

    int lk = tid >> 5;          // 0..7
    int lm = (tid & 31) << 2;   // 0..124 step 4
    const float* Aload = A + (long long)lk * lda + m0 + lm;
    const float* Bload = B + (long long)lk * ldb + n0 + lm;

    int tx = tid & 15, ty = tid >> 4;

    float c[8][8];
#pragma unroll
    for (int i = 0; i < 8; i++)
#pragma unroll
        for (int j = 0; j < 8; j++) c[i][j] = 0.f;

    // preload tile 0 into buffer 0
    float4 av = *(const float4*)(Aload);
    float4 bv = *(const float4*)(Bload);
    *(float4*)(&As[0][lk][lm]) = av;
    *(float4*)(&Bs[0][lk][lm]) = bv;
    __syncthreads();

    int nIter = K / BK;
    for (int it = 0; it < nIter; it++) {
        int buf = it & 1;
        bool more = (it + 1 < nIter);
        if (more) {
            Aload += (long long)BK * lda;
            Bload += (long long)BK * ldb;
            av = *(const float4*)(Aload);
            bv = *(const float4*)(Bload);
        }

#pragma unroll
        for (int kk = 0; kk < BK; kk++) {
            float a[8], b[8];
            *(float4*)(a)     = *(const float4*)(&As[buf][kk][ty * 4]);
            *(float4*)(a + 4) = *(const float4*)(&As[buf][kk][64 + ty * 4]);
            *(float4*)(b)     = *(const float4*)(&Bs[buf][kk][tx * 4]);
            *(float4*)(b + 4) = *(const float4*)(&Bs[buf][kk][64 + tx * 4]);
#pragma unroll
            for (int i = 0; i < 8; i++)
#pragma unroll
                for (int j = 0; j < 8; j++)
                    c[i][j] += a[i] * b[j];
        }

        if (more) {
            *(float4*)(&As[buf ^ 1][lk][lm]) = av;
            *(float4*)(&Bs[buf ^ 1][lk][lm]) = bv;
            __syncthreads();
        }
    }

#pragma unroll
    for (int i = 0; i < 8; i++) {
        int m = m0 + ((i < 4) ? (ty * 4 + i) : (64 + ty * 4 + (i - 4)));
        float bb = bias ? bias[m & 255] : 0.f;
#pragma unroll
        for (int jh = 0; jh < 2; jh++) {
            int n = n0 + jh * 64 + tx * 4;
            float4 v;
            v.x = alpha * c[i][jh * 4 + 0] + bb;
            v.y = alpha * c[i][jh * 4 + 1] + bb;
            v.z = alpha * c[i][jh * 4 + 2] + bb;
            v.w = alpha * c[i][jh * 4 + 3] + bb;
            *(float4*)(&C[(long long)m * ldc + n]) = v;
        }
    }
}

// ---------------------------------------------------------------------------
// 3b) Deterministic ordered reduce of split-K partials with symmetric mirror.
//     Only lower-triangle tiles (tile_m >= tile_n) were computed; upper-tile
//     outputs read the transposed element (L2-resident by then).
// ---------------------------------------------------------------------------
__global__ void reduce_sim_kernel(const float* __restrict__ part, float* __restrict__ sim) {
    int i4 = blockIdx.x * blockDim.x + threadIdx.x;  // 262144
    int i = i4 << 2;
    int m = i >> 10;
    int n = i & 1023;
    const float inv = 1.0f / (float)Bv;
    float4 acc = make_float4(0.f, 0.f, 0.f, 0.f);
    if ((m >> 7) >= (n >> 7)) {
#pragma unroll
        for (int z = 0; z < SPLITK; z++) {
            float4 v = ((const float4*)(part + (long long)z * Nv * Nv))[i4];
            acc.x += v.x; acc.y += v.y; acc.z += v.z; acc.w += v.w;
        }
    } else {
        float a[4] = {0.f, 0.f, 0.f, 0.f};
#pragma unroll
        for (int j = 0; j < 4; j++) {
            long long s = ((long long)(n + j) << 10) + m;
#pragma unroll
            for (int z = 0; z < SPLITK; z++)
                a[j] += part[(long long)z * Nv * Nv + s];
        }
        acc.x = a[0]; acc.y = a[1]; acc.z = a[2]; acc.w = a[3];
    }
    acc.x *= inv; acc.y *= inv; acc.z *= inv; acc.w *= inv;
    ((float4*)sim)[i4] = acc;
}

// ---------------------------------------------------------------------------
// 4) Exact per-row top-k via in-shared bitonic sort (value, 1023-idx) keys.
// ---------------------------------------------------------------------------
__global__ void topk_rows_kernel(const float* __restrict__ sim, float* __restrict__ A) {
    __shared__ unsigned long long s[Nv];
    __shared__ int selfpos;
    int n = blockIdx.x;
    int t = threadIdx.x;  // 512 threads

    for (int i = t; i < Nv; i += 512) {
        unsigned u = __float_as_uint(sim[n * Nv + i]);
        u = (u & 0x80000000u) ? ~u : (u | 0x80000000u);
        s[i] = ((unsigned long long)u << 32) | (unsigned)(1023 - i);
    }
    if (t == 0) selfpos = 0;
    __syncthreads();

    for (unsigned k = 2; k <= (unsigned)Nv; k <<= 1) {
        for (unsigned j = k >> 1; j > 0; j >>= 1) {
            for (int i = t; i < Nv; i += 512) {
                int ixj = i ^ (int)j;
                if (ixj > i) {
                    bool dirDesc = ((i & k) == 0);
                    unsigned long long a = s[i], b = s[ixj];
                    bool sw = dirDesc ? (a < b) : (a > b);
                    if (sw) { s[i] = b; s[ixj] = a; }
                }
            }
            __syncthreads();
        }
    }

    for (int i = t; i < Nv; i += 512) {
        unsigned idx = 1023u - (unsigned)(s[i] & 0xFFFFFFFFu);
        if (idx == (unsigned)n) selfpos = i;
    }
    __syncthreads();
    int sp = selfpos;

    for (int p = t; p < Nv; p += 512) {
        unsigned long long e = s[p];
        unsigned idx = 1023u - (unsigned)(e & 0xFFFFFFFFu);
        unsigned u = (unsigned)(e >> 32);
        u = (u & 0x80000000u) ? (u & 0x7FFFFFFFu) : ~u;
        float v = __uint_as_float(u);
        int rank = p - (p > sp ? 1 : 0);
        bool keep = (p != sp) && (rank < KTOP);
        A[n * Nv + idx] = keep ? v : 0.f;
    }
}

// ---------------------------------------------------------------------------
// 5) in-degree (column sum) -> dinv
// ---------------------------------------------------------------------------
__global__ void deg_kernel(const float* __restrict__ A, float* __restrict__ dinv) {
    int d = blockIdx.x * 256 + threadIdx.x;
    float sum = 0.f;
    for (int src = 0; src < Nv; src++) sum += A[src * Nv + d];
    dinv[d] = (sum > 0.f) ? rsqrtf(sum) : 0.f;
}

// ---------------------------------------------------------------------------
// 6) An[s,d] = dinv[s] * A[s,d] * dinv[d]
// ---------------------------------------------------------------------------
__global__ void an_kernel(const float* __restrict__ A, const float* __restrict__ dinv,
                          float* __restrict__ An) {
    int i = blockIdx.x * 256 + threadIdx.x;
    int src = i >> 10, d = i & 1023;
    An[i] = dinv[src] * A[i] * dinv[d];
}

// ---------------------------------------------------------------------------
// Launch
// ---------------------------------------------------------------------------
extern "C" void kernel_launch(void* const* d_in, const int* in_sizes, int n_in,
                              void* d_out, int out_size) {
    const float* x    = (const float*)d_in[0];   // [32,256,1024]
    const float* W    = (const float*)d_in[1];   // [256,256]
    const float* bias = (const float*)d_in[2];   // [256]
    float* out = (float*)d_out;                  // [32,256,1024]

    float *xhat, *simpart, *sim, *A, *An, *dinv, *invn, *Yt;
    cudaGetSymbolAddress((void**)&xhat,    g_xhat);
    cudaGetSymbolAddress((void**)&simpart, g_simpart);
    cudaGetSymbolAddress((void**)&sim,     g_sim);
    cudaGetSymbolAddress((void**)&A,       g_A);
    cudaGetSymbolAddress((void**)&An,      g_An);
    cudaGetSymbolAddress((void**)&dinv,    g_dinv);
    cudaGetSymbolAddress((void**)&invn,    g_invn);
    cudaGetSymbolAddress((void**)&Yt,      g_Yt);

    // 1) norms
    colsumsq_kernel<<<dim3(Nv / 256, Bv), 256>>>(x, invn);

    // 2) x̂
    scale_x_kernel<<<(BLv * Nv / 4) / 256, 256>>>(x, invn, xhat);

    // 3) Gram split-K, lower-triangle tiles only (36 of 64)
    sgemm_tn<<<dim3(NTRI, 1, SPLITK), 256>>>(
        xhat, xhat, simpart,
        /*K=*/BLv / SPLITK, /*lda=*/Nv, /*ldb=*/Nv, /*ldc=*/Nv,
        /*sA=*/(long long)(BLv / SPLITK) * Nv, /*sB=*/(long long)(BLv / SPLITK) * Nv,
        /*sC=*/(long long)Nv * Nv, 1.0f, nullptr, /*tri=*/1);

    // 3b) ordered reduce + mirror + /B
    reduce_sim_kernel<<<(Nv * Nv / 4) / 256, 256>>>(simpart, sim);

    // 4) exact top-k -> A
    topk_rows_kernel<<<Nv, 512>>>(sim, A);

    // 5) degree -> dinv
    deg_kernel<<<Nv / 256, 256>>>(A, dinv);

    // 6) An
    an_kernel<<<(Nv * Nv) / 256, 256>>>(A, dinv, An);

    // 7) Yt[s, (b,o)] = sum_l x[(b,l),s] * W[l,o]   (batched over b)
    sgemm_tn<<<dim3(Lv / BN, Nv / BM, Bv), 256>>>(
        x, W, Yt,
        /*K=*/Lv, /*lda=*/Nv, /*ldb=*/Lv, /*ldc=*/BLv,
        /*sA=*/(long long)Lv * Nv, /*sB=*/0, /*sC=*/Lv, 1.0f, nullptr, 0);

    // 8) out[k, d] = sum_s Yt[s,k] * An[s,d] + bias[k%256]
    sgemm_tn<<<dim3(Nv / BN, BLv / BM, 1), 256>>>(
        Yt, An, out,
        /*K=*/Nv, /*lda=*/BLv, /*ldb=*/Nv, /*ldc=*/Nv,
        0, 0, 0, 1.0f, bias, 0);
}